// round 6
// baseline (speedup 1.0000x reference)
#include <cuda_runtime.h>
#include <math.h>

// Problem shape (fixed by the dataset)
static const int BATCH = 4;
static const int LQ    = 2048;
static const int SK    = 2048;
static const int D     = 1024;

// Scratch for Q@W (33.5 MB) — __device__ global per alloc rules
__device__ float g_qw[(size_t)BATCH * LQ * D];

// ---------------------------------------------------------------------------
// 128x128x8 register-blocked SGEMM, 256 threads, 8x8 per thread.
// TRANSB=false: C[M,N] = A[M,K] * B[K,N]      (both row-major)
// TRANSB=true : C[M,N] = A[M,K] * B[N,K]^T    (B row-major [N,K])
// Batched via blockIdx.z with element strides sA/sB/sC.
// Requires M,N % 128 == 0 and K % 8 == 0 (true for all three calls).
// ---------------------------------------------------------------------------
template <bool TRANSB>
__global__ __launch_bounds__(256)
void sgemm128(const float* __restrict__ A, const float* __restrict__ Bm,
              float* __restrict__ C, int M, int N, int K,
              long sA, long sB, long sC)
{
    constexpr int BM = 128, BN = 128, BK = 8;
    __shared__ float As[BK][BM];
    __shared__ float Bs[BK][BN];

    const int bz = blockIdx.z;
    const float* Ab = A  + (long)bz * sA;
    const float* Bb = Bm + (long)bz * sB;
    float*       Cb = C  + (long)bz * sC;

    const int tid = threadIdx.x;          // 0..255
    const int tx  = tid & 15;             // 0..15 -> N direction (8 cols each)
    const int ty  = tid >> 4;             // 0..15 -> M direction (8 rows each)
    const int row0 = blockIdx.y * BM;
    const int col0 = blockIdx.x * BN;

    // A-tile (and TRANSB B-tile) load indices: 128 rows x 8 cols, float4/thread
    const int lrow = tid >> 1;            // 0..127
    const int lc4  = (tid & 1) * 4;       // 0 or 4

    float acc[8][8] = {};

    for (int k0 = 0; k0 < K; k0 += BK) {
        // A tile [BM x BK] -> As[k][m] (transposed store)
        {
            float4 av = *reinterpret_cast<const float4*>(
                Ab + (long)(row0 + lrow) * K + k0 + lc4);
            As[lc4 + 0][lrow] = av.x;
            As[lc4 + 1][lrow] = av.y;
            As[lc4 + 2][lrow] = av.z;
            As[lc4 + 3][lrow] = av.w;
        }
        if (TRANSB) {
            // B is [N x K]; tile rows = n, cols = k -> Bs[k][n]
            float4 bv = *reinterpret_cast<const float4*>(
                Bb + (long)(col0 + lrow) * K + k0 + lc4);
            Bs[lc4 + 0][lrow] = bv.x;
            Bs[lc4 + 1][lrow] = bv.y;
            Bs[lc4 + 2][lrow] = bv.z;
            Bs[lc4 + 3][lrow] = bv.w;
        } else {
            // B is [K x N]; tile [BK x BN] row-major, direct float4 store
            const int brow = tid >> 5;          // 0..7
            const int bc4  = (tid & 31) * 4;    // 0..124
            float4 bv = *reinterpret_cast<const float4*>(
                Bb + (long)(k0 + brow) * N + col0 + bc4);
            *reinterpret_cast<float4*>(&Bs[brow][bc4]) = bv;
        }
        __syncthreads();

        #pragma unroll
        for (int k = 0; k < BK; k++) {
            float4 a0 = *reinterpret_cast<const float4*>(&As[k][ty * 8]);
            float4 a1 = *reinterpret_cast<const float4*>(&As[k][ty * 8 + 4]);
            float4 b0 = *reinterpret_cast<const float4*>(&Bs[k][tx * 8]);
            float4 b1 = *reinterpret_cast<const float4*>(&Bs[k][tx * 8 + 4]);
            float ar[8] = {a0.x, a0.y, a0.z, a0.w, a1.x, a1.y, a1.z, a1.w};
            float br[8] = {b0.x, b0.y, b0.z, b0.w, b1.x, b1.y, b1.z, b1.w};
            #pragma unroll
            for (int i = 0; i < 8; i++)
                #pragma unroll
                for (int j = 0; j < 8; j++)
                    acc[i][j] += ar[i] * br[j];
        }
        __syncthreads();
    }

    #pragma unroll
    for (int i = 0; i < 8; i++) {
        float* crow = Cb + (long)(row0 + ty * 8 + i) * N + col0 + tx * 8;
        *reinterpret_cast<float4*>(crow) =
            make_float4(acc[i][0], acc[i][1], acc[i][2], acc[i][3]);
        *reinterpret_cast<float4*>(crow + 4) =
            make_float4(acc[i][4], acc[i][5], acc[i][6], acc[i][7]);
    }
}

// ---------------------------------------------------------------------------
// Masked row softmax over the key dim (SK=2048 per row), in place.
// One block (256 threads) per row; 8 elements per thread in registers.
// Mask read as int32 (bool marshalled as int32 per harness dtype set).
// Masked-out entries -> 0; all-masked row -> uniform 1/SK (matches reference).
// ---------------------------------------------------------------------------
__global__ __launch_bounds__(256)
void softmax_rows(float* __restrict__ S, const int* __restrict__ mask)
{
    const int row = blockIdx.x;                 // 0 .. BATCH*LQ-1
    const int b   = row / LQ;
    float* p = S + (long)row * SK;
    const int* m = mask + (long)b * SK;
    const int t = threadIdx.x;

    __shared__ float red[256];

    float vals[8];
    int mk[8];
    float mx = -INFINITY;
    #pragma unroll
    for (int i = 0; i < 8; i++) {
        const int c = t + i * 256;
        vals[i] = p[c];
        mk[i]   = m[c];
        if (mk[i]) mx = fmaxf(mx, vals[i]);
    }
    red[t] = mx; __syncthreads();
    for (int s = 128; s > 0; s >>= 1) {
        if (t < s) red[t] = fmaxf(red[t], red[t + s]);
        __syncthreads();
    }
    mx = red[0];
    __syncthreads();

    if (!isfinite(mx)) {
        const float u = 1.0f / (float)SK;
        #pragma unroll
        for (int i = 0; i < 8; i++) p[t + i * 256] = u;
        return;
    }

    float sum = 0.f;
    #pragma unroll
    for (int i = 0; i < 8; i++) {
        float e = mk[i] ? expf(vals[i] - mx) : 0.f;
        vals[i] = e;
        sum += e;
    }
    red[t] = sum; __syncthreads();
    for (int s = 128; s > 0; s >>= 1) {
        if (t < s) red[t] += red[t + s];
        __syncthreads();
    }
    const float inv = 1.0f / red[0];
    #pragma unroll
    for (int i = 0; i < 8; i++) p[t + i * 256] = vals[i] * inv;
}

// ---------------------------------------------------------------------------
// kernel_launch: QW -> scores -> softmax -> P@V
// Inputs (metadata order): query, key, value, W, mask
// Output: [output_value (4*2048*1024) | score (4*2048*2048)] fp32
// ---------------------------------------------------------------------------
extern "C" void kernel_launch(void* const* d_in, const int* in_sizes, int n_in,
                              void* d_out, int out_size)
{
    const float* q    = (const float*)d_in[0];
    const float* kk   = (const float*)d_in[1];
    const float* v    = (const float*)d_in[2];
    const float* W    = (const float*)d_in[3];
    const int*   mask = (const int*)d_in[4];

    float* oval  = (float*)d_out;                         // [4,2048,1024]
    float* score = oval + (long)BATCH * LQ * D;           // [4,2048,2048]

    float* qw = nullptr;
    cudaGetSymbolAddress((void**)&qw, g_qw);

    dim3 blk(256);

    // 1. QW = Q @ W : M = n*l = 8192, N = K = 1024
    sgemm128<false><<<dim3(D / 128, (BATCH * LQ) / 128, 1), blk>>>(
        q, W, qw, BATCH * LQ, D, D, 0, 0, 0);

    // 2. S = QW @ K^T per batch : M=2048, N=2048, K=1024
    sgemm128<true><<<dim3(SK / 128, LQ / 128, BATCH), blk>>>(
        qw, kk, score, LQ, SK, D,
        (long)LQ * D, (long)SK * D, (long)LQ * SK);

    // 3. masked softmax over key dim, in place on score
    softmax_rows<<<BATCH * LQ, 256>>>(score, mask);

    // 4. O = P @ V per batch : M=2048, N=1024, K=2048
    sgemm128<false><<<dim3(D / 128, LQ / 128, BATCH), blk>>>(
        score, v, oval, LQ, D, SK,
        (long)LQ * SK, (long)SK * D, (long)LQ * D);
}

// round 9
// speedup vs baseline: 2.2643x; 2.2643x over previous
#include <cuda_runtime.h>
#include <math.h>
#include <stdint.h>

// Problem shape (fixed)
static const int BATCH = 4;
static const int LQ    = 2048;
static const int SK    = 2048;
static const int D     = 1024;

// One static arena, phase-reused (no allocs allowed). 56M floats = 224MB.
//   [0,8M)    qw        (fp32 result of Q@W)
//   [8M,24M)  A-hi      (Qh -> QWh -> Ph)
//   [24M,40M) A-lo
//   [40M,48M) B-hi      (Wth -> Kh -> Vth)
//   [48M,56M) B-lo
#define MF (1024*1024)
__device__ float g_arena[(size_t)56 * MF];

// ---------------------------------------------------------------------------
// helpers
// ---------------------------------------------------------------------------
__device__ __forceinline__ uint32_t smem_u32(const void* p) {
    uint32_t a;
    asm("{ .reg .u64 t; cvta.to.shared.u64 t, %1; cvt.u32.u64 %0, t; }"
        : "=r"(a) : "l"(p));
    return a;
}

__device__ __forceinline__ void cp_async16(uint32_t s, const void* g) {
    asm volatile("cp.async.cg.shared.global [%0], [%1], 16;" :: "r"(s), "l"(g));
}

__device__ __forceinline__ float tf32_rna(float x) {
    uint32_t u;
    asm("cvt.rna.tf32.f32 %0, %1;" : "=r"(u) : "f"(x));
    return __uint_as_float(u);
}

__device__ __forceinline__ void mma_tf32(float* c, const uint32_t* a,
                                         const uint32_t* b) {
    asm volatile(
        "mma.sync.aligned.m16n8k8.row.col.f32.tf32.tf32.f32 "
        "{%0,%1,%2,%3}, {%4,%5,%6,%7}, {%8,%9}, {%0,%1,%2,%3};"
        : "+f"(c[0]), "+f"(c[1]), "+f"(c[2]), "+f"(c[3])
        : "r"(a[0]), "r"(a[1]), "r"(a[2]), "r"(a[3]), "r"(b[0]), "r"(b[1]));
}

// ---------------------------------------------------------------------------
// Elementwise tf32 split: h = tf32(x), l = tf32(x - h).  n % 1024 == 0.
// ---------------------------------------------------------------------------
__global__ __launch_bounds__(256)
void split_tf32(const float4* __restrict__ in, float4* __restrict__ h,
                float4* __restrict__ l)
{
    const long i = (long)blockIdx.x * 256 + threadIdx.x;
    float4 x = in[i];
    float4 hh, ll;
    hh.x = tf32_rna(x.x); ll.x = tf32_rna(x.x - hh.x);
    hh.y = tf32_rna(x.y); ll.y = tf32_rna(x.y - hh.y);
    hh.z = tf32_rna(x.z); ll.z = tf32_rna(x.z - hh.z);
    hh.w = tf32_rna(x.w); ll.w = tf32_rna(x.w - hh.w);
    h[i] = hh; l[i] = ll;
}

// ---------------------------------------------------------------------------
// Transpose + split: out_{h,l}[c][r] = split(in[r][c]).  32x32 tiles.
// ---------------------------------------------------------------------------
__global__ __launch_bounds__(256)
void transpose_split(const float* __restrict__ in, float* __restrict__ oh,
                     float* __restrict__ ol, int R, int Cn, long sIn, long sOut)
{
    __shared__ float t[32][33];
    const float* ib = in + (long)blockIdx.z * sIn;
    float* ohb = oh + (long)blockIdx.z * sOut;
    float* olb = ol + (long)blockIdx.z * sOut;
    const int r0 = blockIdx.y * 32, c0 = blockIdx.x * 32;
    const int tx = threadIdx.x & 31, ty = threadIdx.x >> 5;   // 32x8
    #pragma unroll
    for (int i = 0; i < 32; i += 8)
        t[ty + i][tx] = ib[(long)(r0 + ty + i) * Cn + c0 + tx];
    __syncthreads();
    #pragma unroll
    for (int i = 0; i < 32; i += 8) {
        float x = t[tx][ty + i];
        float h = tf32_rna(x);
        long  o = (long)(c0 + ty + i) * R + r0 + tx;
        ohb[o] = h;
        olb[o] = tf32_rna(x - h);
    }
}

// ---------------------------------------------------------------------------
// 3xTF32 GEMM (NT) via mma.sync.m16n8k8:
//   C[M,N] = (Ah+Al)[M,K] * ((Bh+Bl)[N,K])^T  (3-term split product)
// CTA tile 128x128, BK=32, 8 warps (2m x 4n), warp tile 64x32.
// cp.async 2-stage double buffer. SMEM rows padded to 36 floats.
// ---------------------------------------------------------------------------
__global__ __launch_bounds__(256, 1)
void mma3gemm(const float* __restrict__ Ah, const float* __restrict__ Al,
              const float* __restrict__ Bh, const float* __restrict__ Bl,
              float* __restrict__ C, int K, int ldc,
              long sA, long sB, long sC)
{
    extern __shared__ float sm[];
    const uint32_t sbase = smem_u32(sm);

    const int tid = threadIdx.x, lane = tid & 31, wid = tid >> 5;
    const int warp_m = wid & 1, warp_n = wid >> 1;
    const int gid = lane >> 2, tnum = lane & 3;
    const int row0 = blockIdx.y * 128, col0 = blockIdx.x * 128;
    const long zb = blockIdx.z;

    const float* gT[4] = {
        Ah + zb * sA + (long)row0 * K,
        Al + zb * sA + (long)row0 * K,
        Bh + zb * sB + (long)col0 * K,
        Bl + zb * sB + (long)col0 * K
    };
    float* Cb = C + zb * sC;

    // stage (floats): 4 tiles x 128 rows x 36 = 18432; tile stride 4608
    const int niter = K >> 5;

    auto load_stage = [&](int it, int stage) {
        const int kk = it * 32;
        #pragma unroll
        for (int t = 0; t < 16; t++) {
            int c    = t * 256 + tid;
            int tile = c >> 10;
            int row  = (c >> 3) & 127;
            int seg  = c & 7;
            const float* g = gT[tile] + (long)row * K + kk + seg * 4;
            uint32_t s = sbase +
                (uint32_t)(stage * 18432 + tile * 4608 + row * 36 + seg * 4) * 4u;
            cp_async16(s, g);
        }
    };

    float acc[4][4][4] = {};

    load_stage(0, 0);
    asm volatile("cp.async.commit_group;" ::: "memory");
    load_stage(1, 1);
    asm volatile("cp.async.commit_group;" ::: "memory");

    for (int it = 0; it < niter; ++it) {
        asm volatile("cp.async.wait_group 1;" ::: "memory");
        __syncthreads();

        const float* st  = sm + (it & 1) * 18432;
        const float* sAh = st;
        const float* sAl = st + 4608;
        const float* sBh = st + 9216;
        const float* sBl = st + 13824;

        #pragma unroll
        for (int k8 = 0; k8 < 4; k8++) {
            const int kx = k8 * 8 + tnum;

            uint32_t bh[4][2], bl[4][2];
            #pragma unroll
            for (int j = 0; j < 4; j++) {
                int n = warp_n * 32 + j * 8 + gid;
                bh[j][0] = __float_as_uint(sBh[n * 36 + kx]);
                bh[j][1] = __float_as_uint(sBh[n * 36 + kx + 4]);
                bl[j][0] = __float_as_uint(sBl[n * 36 + kx]);
                bl[j][1] = __float_as_uint(sBl[n * 36 + kx + 4]);
            }
            #pragma unroll
            for (int i = 0; i < 4; i++) {
                int r = warp_m * 64 + i * 16 + gid;
                uint32_t ah[4], al[4];
                ah[0] = __float_as_uint(sAh[r * 36 + kx]);
                ah[1] = __float_as_uint(sAh[(r + 8) * 36 + kx]);
                ah[2] = __float_as_uint(sAh[r * 36 + kx + 4]);
                ah[3] = __float_as_uint(sAh[(r + 8) * 36 + kx + 4]);
                al[0] = __float_as_uint(sAl[r * 36 + kx]);
                al[1] = __float_as_uint(sAl[(r + 8) * 36 + kx]);
                al[2] = __float_as_uint(sAl[r * 36 + kx + 4]);
                al[3] = __float_as_uint(sAl[(r + 8) * 36 + kx + 4]);
                #pragma unroll
                for (int j = 0; j < 4; j++) {
                    mma_tf32(acc[i][j], ah, bh[j]);   // hi*hi
                    mma_tf32(acc[i][j], ah, bl[j]);   // hi*lo
                    mma_tf32(acc[i][j], al, bh[j]);   // lo*hi
                }
            }
        }
        __syncthreads();
        if (it + 2 < niter) load_stage(it + 2, it & 1);
        asm volatile("cp.async.commit_group;" ::: "memory");
    }

    // Epilogue: direct float2 stores (c0,c1) rows r, (c2,c3) rows r+8
    #pragma unroll
    for (int i = 0; i < 4; i++) {
        const int r = row0 + warp_m * 64 + i * 16 + gid;
        #pragma unroll
        for (int j = 0; j < 4; j++) {
            const int cc = col0 + warp_n * 32 + j * 8 + 2 * tnum;
            float2 v0 = make_float2(acc[i][j][0], acc[i][j][1]);
            float2 v1 = make_float2(acc[i][j][2], acc[i][j][3]);
            *reinterpret_cast<float2*>(&Cb[(long)r * ldc + cc])       = v0;
            *reinterpret_cast<float2*>(&Cb[(long)(r + 8) * ldc + cc]) = v1;
        }
    }
}

// ---------------------------------------------------------------------------
// Masked row softmax over key dim (SK=2048), in place. Mask is int32.
// ---------------------------------------------------------------------------
__global__ __launch_bounds__(256)
void softmax_rows(float* __restrict__ S, const int* __restrict__ mask)
{
    const int row = blockIdx.x;
    const int b   = row / LQ;
    float* p = S + (long)row * SK;
    const int* m = mask + (long)b * SK;
    const int t = threadIdx.x;

    __shared__ float red[256];

    float vals[8];
    int mk[8];
    float mx = -INFINITY;
    #pragma unroll
    for (int i = 0; i < 8; i++) {
        const int c = t + i * 256;
        vals[i] = p[c];
        mk[i]   = m[c];
        if (mk[i]) mx = fmaxf(mx, vals[i]);
    }
    red[t] = mx; __syncthreads();
    for (int s = 128; s > 0; s >>= 1) {
        if (t < s) red[t] = fmaxf(red[t], red[t + s]);
        __syncthreads();
    }
    mx = red[0];
    __syncthreads();

    if (!isfinite(mx)) {
        const float u = 1.0f / (float)SK;
        #pragma unroll
        for (int i = 0; i < 8; i++) p[t + i * 256] = u;
        return;
    }

    float sum = 0.f;
    #pragma unroll
    for (int i = 0; i < 8; i++) {
        float e = mk[i] ? expf(vals[i] - mx) : 0.f;
        vals[i] = e;
        sum += e;
    }
    red[t] = sum; __syncthreads();
    for (int s = 128; s > 0; s >>= 1) {
        if (t < s) red[t] += red[t + s];
        __syncthreads();
    }
    const float inv = 1.0f / red[0];
    #pragma unroll
    for (int i = 0; i < 8; i++) p[t + i * 256] = vals[i] * inv;
}

// ---------------------------------------------------------------------------
// kernel_launch
// Inputs: query, key, value, W, mask. Output: [output_value | score] fp32.
// ---------------------------------------------------------------------------
extern "C" void kernel_launch(void* const* d_in, const int* in_sizes, int n_in,
                              void* d_out, int out_size)
{
    const float* q    = (const float*)d_in[0];
    const float* kk   = (const float*)d_in[1];
    const float* v    = (const float*)d_in[2];
    const float* W    = (const float*)d_in[3];
    const int*   mask = (const int*)d_in[4];

    float* oval  = (float*)d_out;                       // [4,2048,1024]
    float* score = oval + (long)BATCH * LQ * D;         // [4,2048,2048]

    float* arena = nullptr;
    cudaGetSymbolAddress((void**)&arena, g_arena);
    float* qw = arena;                                  // 8M
    float* Axh = arena + (long) 8 * MF;                 // 16M
    float* Axl = arena + (long)24 * MF;                 // 16M
    float* Bxh = arena + (long)40 * MF;                 // 8M
    float* Bxl = arena + (long)48 * MF;                 // 8M

    const int SMEM_BYTES = 2 * 18432 * 4;               // 147456
    static bool attr_set = false;
    if (!attr_set) {
        cudaFuncSetAttribute(mma3gemm,
            cudaFuncAttributeMaxDynamicSharedMemorySize, SMEM_BYTES);
        attr_set = true;
    }

    // ---- Phase 1: QW = Q @ W  (M=8192, N=1024, K=1024) ----
    transpose_split<<<dim3(D / 32, D / 32, 1), 256>>>(
        W, Bxh, Bxl, D, D, 0, 0);
    split_tf32<<<(BATCH * LQ * (long)D) / 1024, 256>>>(
        (const float4*)q, (float4*)Axh, (float4*)Axl);
    mma3gemm<<<dim3(D / 128, (BATCH * LQ) / 128, 1), 256, SMEM_BYTES>>>(
        Axh, Axl, Bxh, Bxl, qw, D, D, 0, 0, 0);

    // ---- Phase 2: S = QW @ K^T per batch (M=2048, N=2048, K=1024) ----
    split_tf32<<<(BATCH * LQ * (long)D) / 1024, 256>>>(
        (const float4*)qw, (float4*)Axh, (float4*)Axl);
    split_tf32<<<(BATCH * SK * (long)D) / 1024, 256>>>(
        (const float4*)kk, (float4*)Bxh, (float4*)Bxl);
    mma3gemm<<<dim3(SK / 128, LQ / 128, BATCH), 256, SMEM_BYTES>>>(
        Axh, Axl, Bxh, Bxl, score, D, SK,
        (long)LQ * D, (long)SK * D, (long)LQ * SK);

    // ---- Phase 3: softmax, then O = P @ V per batch (M=2048,N=1024,K=2048) ----
    softmax_rows<<<BATCH * LQ, 256>>>(score, mask);
    split_tf32<<<(BATCH * LQ * (long)SK) / 1024, 256>>>(
        (const float4*)score, (float4*)Axh, (float4*)Axl);
    transpose_split<<<dim3(D / 32, SK / 32, BATCH), 256>>>(
        v, Bxh, Bxl, SK, D, (long)SK * D, (long)D * SK);
    mma3gemm<<<dim3(D / 128, LQ / 128, BATCH), 256, SMEM_BYTES>>>(
        Axh, Axl, Bxh, Bxl, oval, SK, D,
        (long)LQ * SK, (long)D * SK, (long)LQ * D);
}

// round 12
// speedup vs baseline: 4.1370x; 1.8271x over previous
#include <cuda_runtime.h>
#include <cuda_fp16.h>
#include <math.h>
#include <stdint.h>

// Problem shape (fixed)
static const int BATCH = 4;
static const int LQ    = 2048;
static const int SK    = 2048;
static const int D     = 1024;

// Static arena (no allocs). Layout in __half units:
//   A1h @ 0    (8M)  : Q hi            [8192,1024]
//   A1l @ 8M   (8M)  : Q lo
//   Bh  @ 16M  (8M)  : W^T / K / V^T hi
//   Bl  @ 24M  (8M)  : lo
//   A2h @ 32M  (16M) : QW hi -> P hi   [8192,1024] then [8192,2048]
//   A2l @ 48M  (16M) : lo
#define MH (1024*1024)
__device__ __half g_arena[(size_t)64 * MH];

// ---------------------------------------------------------------------------
// helpers
// ---------------------------------------------------------------------------
__device__ __forceinline__ uint32_t smem_u32(const void* p) {
    uint32_t a;
    asm("{ .reg .u64 t; cvta.to.shared.u64 t, %1; cvt.u32.u64 %0, t; }"
        : "=r"(a) : "l"(p));
    return a;
}

__device__ __forceinline__ void cp_async16(uint32_t s, const void* g) {
    asm volatile("cp.async.cg.shared.global [%0], [%1], 16;" :: "r"(s), "l"(g));
}

__device__ __forceinline__ uint32_t ld32(const __half* p) {
    return *reinterpret_cast<const uint32_t*>(p);
}

__device__ __forceinline__ void mma_f16(float* c, const uint32_t* a,
                                        const uint32_t* b) {
    asm volatile(
        "mma.sync.aligned.m16n8k16.row.col.f32.f16.f16.f32 "
        "{%0,%1,%2,%3}, {%4,%5,%6,%7}, {%8,%9}, {%0,%1,%2,%3};"
        : "+f"(c[0]), "+f"(c[1]), "+f"(c[2]), "+f"(c[3])
        : "r"(a[0]), "r"(a[1]), "r"(a[2]), "r"(a[3]), "r"(b[0]), "r"(b[1]));
}

__device__ __forceinline__ void split_h(float x, __half& h, __half& l) {
    h = __float2half_rn(x);
    l = __float2half_rn(x - __half2float(h));
}

// ---------------------------------------------------------------------------
// Elementwise fp16 split: h = f16(x), l = f16(x - h).  n % 1024 == 0.
// ---------------------------------------------------------------------------
__global__ __launch_bounds__(256)
void split_f16(const float4* __restrict__ in, __half2* __restrict__ h,
               __half2* __restrict__ l)
{
    const long i = (long)blockIdx.x * 256 + threadIdx.x;
    float4 x = in[i];
    __half hx, lx, hy, ly, hz, lz, hw, lw;
    split_h(x.x, hx, lx); split_h(x.y, hy, ly);
    split_h(x.z, hz, lz); split_h(x.w, hw, lw);
    h[2 * i]     = __halves2half2(hx, hy);
    h[2 * i + 1] = __halves2half2(hz, hw);
    l[2 * i]     = __halves2half2(lx, ly);
    l[2 * i + 1] = __halves2half2(lz, lw);
}

// ---------------------------------------------------------------------------
// Transpose + fp16 split: out_{h,l}[c][r] = split(in[r][c]).  32x32 tiles.
// ---------------------------------------------------------------------------
__global__ __launch_bounds__(256)
void transpose_split(const float* __restrict__ in, __half* __restrict__ oh,
                     __half* __restrict__ ol, int R, int Cn, long sIn, long sOut)
{
    __shared__ float t[32][33];
    const float* ib = in + (long)blockIdx.z * sIn;
    __half* ohb = oh + (long)blockIdx.z * sOut;
    __half* olb = ol + (long)blockIdx.z * sOut;
    const int r0 = blockIdx.y * 32, c0 = blockIdx.x * 32;
    const int tx = threadIdx.x & 31, ty = threadIdx.x >> 5;   // 32x8
    #pragma unroll
    for (int i = 0; i < 32; i += 8)
        t[ty + i][tx] = ib[(long)(r0 + ty + i) * Cn + c0 + tx];
    __syncthreads();
    #pragma unroll
    for (int i = 0; i < 32; i += 8) {
        __half h, l;
        split_h(t[tx][ty + i], h, l);
        long o = (long)(c0 + ty + i) * R + r0 + tx;
        ohb[o] = h;
        olb[o] = l;
    }
}

// ---------------------------------------------------------------------------
// fp16x3 GEMM (NT) via mma.sync.m16n8k16:
//   C[M,N] = (Ah+Al)[M,K] * ((Bh+Bl)[N,K])^T   (3-term: hh + hl + lh)
// CTA 128x128, BK=32, 8 warps (2m x 4n), warp tile 64x32.
// cp.async 3-stage pipeline. SMEM rows padded to 40 halves (80 B).
// SPLITOUT: write C as fp16 hi/lo pair instead of fp32.
// ---------------------------------------------------------------------------
template <bool SPLITOUT>
__global__ __launch_bounds__(256, 1)
void mma3gemm(const __half* __restrict__ Ah, const __half* __restrict__ Al,
              const __half* __restrict__ Bh, const __half* __restrict__ Bl,
              float* __restrict__ C, __half* __restrict__ Ch,
              __half* __restrict__ Cl, int K, int ldc,
              long sA, long sB, long sC)
{
    extern __shared__ __half smh[];
    const uint32_t sbase = smem_u32(smh);

    const int tid = threadIdx.x, lane = tid & 31, wid = tid >> 5;
    const int warp_m = wid & 1, warp_n = wid >> 1;
    const int gid = lane >> 2, tnum = lane & 3;
    const int row0 = blockIdx.y * 128, col0 = blockIdx.x * 128;
    const long zb = blockIdx.z;

    const __half* gT[4] = {
        Ah + zb * sA + (long)row0 * K,
        Al + zb * sA + (long)row0 * K,
        Bh + zb * sB + (long)col0 * K,
        Bl + zb * sB + (long)col0 * K
    };

    // stage: 4 tiles x 128 rows x 40 halves = 20480 halves (40960 B)
    const int niter = K >> 5;

    auto load_stage = [&](int it, int stage) {
        const int kk = it * 32;
        #pragma unroll
        for (int t = 0; t < 8; t++) {
            int c    = t * 256 + tid;
            int tile = c >> 9;             // 512 cp.async per tile
            int row  = (c >> 2) & 127;
            int seg  = c & 3;              // 4 x 8-half segments per row
            const __half* g = gT[tile] + (long)row * K + kk + seg * 8;
            uint32_t s = sbase +
                (uint32_t)(stage * 40960 + tile * 10240 + row * 80 + seg * 16);
            cp_async16(s, g);
        }
    };

    float acc[4][4][4] = {};

    load_stage(0, 0);
    asm volatile("cp.async.commit_group;" ::: "memory");
    load_stage(1, 1);
    asm volatile("cp.async.commit_group;" ::: "memory");
    load_stage(2, 2);
    asm volatile("cp.async.commit_group;" ::: "memory");

    for (int it = 0; it < niter; ++it) {
        asm volatile("cp.async.wait_group 2;" ::: "memory");
        __syncthreads();

        const int buf = it % 3;
        const __half* st  = smh + buf * 20480;
        const __half* sAh = st;
        const __half* sAl = st + 5120;
        const __half* sBh = st + 10240;
        const __half* sBl = st + 15360;

        #pragma unroll
        for (int k16 = 0; k16 < 2; k16++) {
            const int kb = k16 * 16 + 2 * tnum;   // first half of k-pair

            uint32_t bh[4][2], bl[4][2];
            #pragma unroll
            for (int j = 0; j < 4; j++) {
                const int n = warp_n * 32 + j * 8 + gid;
                const __half* pb = sBh + n * 40 + kb;
                const __half* ql = sBl + n * 40 + kb;
                bh[j][0] = ld32(pb);     bh[j][1] = ld32(pb + 8);
                bl[j][0] = ld32(ql);     bl[j][1] = ld32(ql + 8);
            }
            #pragma unroll
            for (int i = 0; i < 4; i++) {
                const int r = warp_m * 64 + i * 16 + gid;
                const __half* pa = sAh + r * 40 + kb;
                const __half* qa = sAl + r * 40 + kb;
                uint32_t ah[4], al[4];
                ah[0] = ld32(pa);        ah[1] = ld32(pa + 320);   // r+8
                ah[2] = ld32(pa + 8);    ah[3] = ld32(pa + 328);
                al[0] = ld32(qa);        al[1] = ld32(qa + 320);
                al[2] = ld32(qa + 8);    al[3] = ld32(qa + 328);
                #pragma unroll
                for (int j = 0; j < 4; j++) {
                    mma_f16(acc[i][j], ah, bh[j]);   // hi*hi
                    mma_f16(acc[i][j], ah, bl[j]);   // hi*lo
                    mma_f16(acc[i][j], al, bh[j]);   // lo*hi
                }
            }
        }
        __syncthreads();
        if (it + 3 < niter) load_stage(it + 3, buf);
        asm volatile("cp.async.commit_group;" ::: "memory");
    }

    // Epilogue
    #pragma unroll
    for (int i = 0; i < 4; i++) {
        const int r = row0 + warp_m * 64 + i * 16 + gid;
        #pragma unroll
        for (int j = 0; j < 4; j++) {
            const int cc = col0 + warp_n * 32 + j * 8 + 2 * tnum;
            if (SPLITOUT) {
                __half h0, l0, h1, l1;
                long o0 = (long)r * ldc + cc + zb * sC;
                long o1 = (long)(r + 8) * ldc + cc + zb * sC;
                split_h(acc[i][j][0], h0, l0);
                split_h(acc[i][j][1], h1, l1);
                *reinterpret_cast<__half2*>(Ch + o0) = __halves2half2(h0, h1);
                *reinterpret_cast<__half2*>(Cl + o0) = __halves2half2(l0, l1);
                split_h(acc[i][j][2], h0, l0);
                split_h(acc[i][j][3], h1, l1);
                *reinterpret_cast<__half2*>(Ch + o1) = __halves2half2(h0, h1);
                *reinterpret_cast<__half2*>(Cl + o1) = __halves2half2(l0, l1);
            } else {
                float* Cb = C + zb * sC;
                *reinterpret_cast<float2*>(&Cb[(long)r * ldc + cc]) =
                    make_float2(acc[i][j][0], acc[i][j][1]);
                *reinterpret_cast<float2*>(&Cb[(long)(r + 8) * ldc + cc]) =
                    make_float2(acc[i][j][2], acc[i][j][3]);
            }
        }
    }
}

// ---------------------------------------------------------------------------
// Masked row softmax (SK=2048) in place + fused fp16 split of the result.
// Mask is int32. All-masked row -> uniform 1/SK.
// ---------------------------------------------------------------------------
__global__ __launch_bounds__(256)
void softmax_split(float* __restrict__ S, const int* __restrict__ mask,
                   __half* __restrict__ Ph, __half* __restrict__ Pl)
{
    const int row = blockIdx.x;
    const int b   = row / LQ;
    float* p = S + (long)row * SK;
    __half* ph = Ph + (long)row * SK;
    __half* pl = Pl + (long)row * SK;
    const int* m = mask + (long)b * SK;
    const int t = threadIdx.x;

    __shared__ float red[256];

    float vals[8];
    int mk[8];
    float mx = -INFINITY;
    #pragma unroll
    for (int i = 0; i < 8; i++) {
        const int c = t + i * 256;
        vals[i] = p[c];
        mk[i]   = m[c];
        if (mk[i]) mx = fmaxf(mx, vals[i]);
    }
    red[t] = mx; __syncthreads();
    for (int s = 128; s > 0; s >>= 1) {
        if (t < s) red[t] = fmaxf(red[t], red[t + s]);
        __syncthreads();
    }
    mx = red[0];
    __syncthreads();

    if (!isfinite(mx)) {
        const float u = 1.0f / (float)SK;
        __half uh, ul;
        split_h(u, uh, ul);
        #pragma unroll
        for (int i = 0; i < 8; i++) {
            p[t + i * 256]  = u;
            ph[t + i * 256] = uh;
            pl[t + i * 256] = ul;
        }
        return;
    }

    float sum = 0.f;
    #pragma unroll
    for (int i = 0; i < 8; i++) {
        float e = mk[i] ? expf(vals[i] - mx) : 0.f;
        vals[i] = e;
        sum += e;
    }
    red[t] = sum; __syncthreads();
    for (int s = 128; s > 0; s >>= 1) {
        if (t < s) red[t] += red[t + s];
        __syncthreads();
    }
    const float inv = 1.0f / red[0];
    #pragma unroll
    for (int i = 0; i < 8; i++) {
        const int c = t + i * 256;
        float pv = vals[i] * inv;
        p[c] = pv;
        __half h, l;
        split_h(pv, h, l);
        ph[c] = h;
        pl[c] = l;
    }
}

// ---------------------------------------------------------------------------
// kernel_launch
// Inputs: query, key, value, W, mask. Output: [output_value | score] fp32.
// ---------------------------------------------------------------------------
extern "C" void kernel_launch(void* const* d_in, const int* in_sizes, int n_in,
                              void* d_out, int out_size)
{
    const float* q    = (const float*)d_in[0];
    const float* kk   = (const float*)d_in[1];
    const float* v    = (const float*)d_in[2];
    const float* W    = (const float*)d_in[3];
    const int*   mask = (const int*)d_in[4];

    float* oval  = (float*)d_out;                       // [4,2048,1024]
    float* score = oval + (long)BATCH * LQ * D;         // [4,2048,2048]

    __half* arena = nullptr;
    cudaGetSymbolAddress((void**)&arena, g_arena);
    __half* A1h = arena;                                // 8M
    __half* A1l = arena + (long) 8 * MH;                // 8M
    __half* Bh  = arena + (long)16 * MH;                // 8M
    __half* Bl  = arena + (long)24 * MH;                // 8M
    __half* A2h = arena + (long)32 * MH;                // 16M
    __half* A2l = arena + (long)48 * MH;                // 16M

    const int SMEM_BYTES = 3 * 40960;                   // 122880
    static bool attr_set = false;
    if (!attr_set) {
        cudaFuncSetAttribute(mma3gemm<true>,
            cudaFuncAttributeMaxDynamicSharedMemorySize, SMEM_BYTES);
        cudaFuncSetAttribute(mma3gemm<false>,
            cudaFuncAttributeMaxDynamicSharedMemorySize, SMEM_BYTES);
        attr_set = true;
    }

    // ---- Phase 1: QW = Q @ W, result written directly as split halves ----
    split_f16<<<(BATCH * LQ * (long)D) / 1024, 256>>>(
        (const float4*)q, (__half2*)A1h, (__half2*)A1l);
    transpose_split<<<dim3(D / 32, D / 32, 1), 256>>>(W, Bh, Bl, D, D, 0, 0);
    mma3gemm<true><<<dim3(D / 128, (BATCH * LQ) / 128, 1), 256, SMEM_BYTES>>>(
        A1h, A1l, Bh, Bl, nullptr, A2h, A2l, D, D, 0, 0, 0);

    // ---- Phase 2: S = QW @ K^T per batch ----
    split_f16<<<(BATCH * SK * (long)D) / 1024, 256>>>(
        (const float4*)kk, (__half2*)Bh, (__half2*)Bl);
    mma3gemm<false><<<dim3(SK / 128, LQ / 128, BATCH), 256, SMEM_BYTES>>>(
        A2h, A2l, Bh, Bl, score, nullptr, nullptr, D, SK,
        (long)LQ * D, (long)SK * D, (long)LQ * SK);

    // ---- Phase 3: softmax (+fused split), then O = P @ V per batch ----
    softmax_split<<<BATCH * LQ, 256>>>(score, mask, A2h, A2l);
    transpose_split<<<dim3(D / 32, SK / 32, BATCH), 256>>>(
        v, Bh, Bl, SK, D, (long)SK * D, (long)D * SK);
    mma3gemm<false><<<dim3(D / 128, LQ / 128, BATCH), 256, SMEM_BYTES>>>(
        A2h, A2l, Bh, Bl, oval, nullptr, nullptr, SK, D,
        (long)LQ * SK, (long)D * SK, (long)LQ * D);
}

// round 14
// speedup vs baseline: 4.2728x; 1.0328x over previous
#include <cuda_runtime.h>
#include <cuda_fp16.h>
#include <math.h>
#include <stdint.h>

// Problem shape (fixed)
static const int BATCH = 4;
static const int LQ    = 2048;
static const int SK    = 2048;
static const int D     = 1024;

// Static arena (no allocs). Layout in __half units:
//   A1h @ 0    (8M)  : Q hi            [8192,1024]
//   A1l @ 8M   (8M)  : Q lo
//   Bh  @ 16M  (8M)  : W^T / K / V^T hi
//   Bl  @ 24M  (8M)  : lo
//   A2h @ 32M  (16M) : QW hi -> P (single fp16)  [8192,1024] then [8192,2048]
//   A2l @ 48M  (16M) : QW lo
#define MH (1024*1024)
__device__ __half g_arena[(size_t)64 * MH];

// ---------------------------------------------------------------------------
// helpers
// ---------------------------------------------------------------------------
__device__ __forceinline__ uint32_t smem_u32(const void* p) {
    uint32_t a;
    asm("{ .reg .u64 t; cvta.to.shared.u64 t, %1; cvt.u32.u64 %0, t; }"
        : "=r"(a) : "l"(p));
    return a;
}

__device__ __forceinline__ void cp_async16(uint32_t s, const void* g) {
    asm volatile("cp.async.cg.shared.global [%0], [%1], 16;" :: "r"(s), "l"(g));
}

__device__ __forceinline__ uint32_t ld32(const __half* p) {
    return *reinterpret_cast<const uint32_t*>(p);
}

__device__ __forceinline__ void mma_f16(float* c, const uint32_t* a,
                                        const uint32_t* b) {
    asm volatile(
        "mma.sync.aligned.m16n8k16.row.col.f32.f16.f16.f32 "
        "{%0,%1,%2,%3}, {%4,%5,%6,%7}, {%8,%9}, {%0,%1,%2,%3};"
        : "+f"(c[0]), "+f"(c[1]), "+f"(c[2]), "+f"(c[3])
        : "r"(a[0]), "r"(a[1]), "r"(a[2]), "r"(a[3]), "r"(b[0]), "r"(b[1]));
}

__device__ __forceinline__ void split_h(float x, __half& h, __half& l) {
    h = __float2half_rn(x);
    l = __float2half_rn(x - __half2float(h));
}

// ---------------------------------------------------------------------------
// Elementwise fp16 split: h = f16(x), l = f16(x - h).  n % 1024 == 0.
// ---------------------------------------------------------------------------
__global__ __launch_bounds__(256)
void split_f16(const float4* __restrict__ in, __half2* __restrict__ h,
               __half2* __restrict__ l)
{
    const long i = (long)blockIdx.x * 256 + threadIdx.x;
    float4 x = in[i];
    __half hx, lx, hy, ly, hz, lz, hw, lw;
    split_h(x.x, hx, lx); split_h(x.y, hy, ly);
    split_h(x.z, hz, lz); split_h(x.w, hw, lw);
    h[2 * i]     = __halves2half2(hx, hy);
    h[2 * i + 1] = __halves2half2(hz, hw);
    l[2 * i]     = __halves2half2(lx, ly);
    l[2 * i + 1] = __halves2half2(lz, lw);
}

// ---------------------------------------------------------------------------
// Transpose + fp16 split: out_{h,l}[c][r] = split(in[r][c]).  32x32 tiles.
// ---------------------------------------------------------------------------
__global__ __launch_bounds__(256)
void transpose_split(const float* __restrict__ in, __half* __restrict__ oh,
                     __half* __restrict__ ol, int R, int Cn, long sIn, long sOut)
{
    __shared__ float t[32][33];
    const float* ib = in + (long)blockIdx.z * sIn;
    __half* ohb = oh + (long)blockIdx.z * sOut;
    __half* olb = ol + (long)blockIdx.z * sOut;
    const int r0 = blockIdx.y * 32, c0 = blockIdx.x * 32;
    const int tx = threadIdx.x & 31, ty = threadIdx.x >> 5;   // 32x8
    #pragma unroll
    for (int i = 0; i < 32; i += 8)
        t[ty + i][tx] = ib[(long)(r0 + ty + i) * Cn + c0 + tx];
    __syncthreads();
    #pragma unroll
    for (int i = 0; i < 32; i += 8) {
        __half h, l;
        split_h(t[tx][ty + i], h, l);
        long o = (long)(c0 + ty + i) * R + r0 + tx;
        ohb[o] = h;
        olb[o] = l;
    }
}

// ---------------------------------------------------------------------------
// fp16 multi-term GEMM (NT) via mma.sync.m16n8k16:
// TERMS=3: C = (Ah+Al)(Bh+Bl)^T   (hh + hl + lh)   tiles {Ah,Al,Bh,Bl}
// TERMS=2: C = Ah(Bh+Bl)^T        (h  + l)         tiles {Ah,Bh,Bl}
// CTA 128x128, BK=32, 8 warps (2m x 4n), warp tile 64x32.
// cp.async 3-stage pipeline. SMEM rows padded to 40 halves (80 B).
// SPLITOUT: write C as fp16 hi/lo pair instead of fp32.
// ---------------------------------------------------------------------------
template <int TERMS, bool SPLITOUT>
__global__ __launch_bounds__(256)
void mma3gemm(const __half* __restrict__ Ah, const __half* __restrict__ Al,
              const __half* __restrict__ Bh, const __half* __restrict__ Bl,
              float* __restrict__ C, __half* __restrict__ Ch,
              __half* __restrict__ Cl, int K, int ldc,
              long sA, long sB, long sC)
{
    constexpr int TILES = (TERMS == 3) ? 4 : 3;
    constexpr int STAGE_H = TILES * 5120;           // halves per stage
    constexpr int STAGE_B = STAGE_H * 2;            // bytes per stage

    extern __shared__ __half smh[];
    const uint32_t sbase = smem_u32(smh);

    const int tid = threadIdx.x, lane = tid & 31, wid = tid >> 5;
    const int warp_m = wid & 1, warp_n = wid >> 1;
    const int gid = lane >> 2, tnum = lane & 3;
    const int row0 = blockIdx.y * 128, col0 = blockIdx.x * 128;
    const long zb = blockIdx.z;

    const __half* gT[TILES];
    gT[0] = Ah + zb * sA + (long)row0 * K;
    if (TERMS == 3) {
        gT[1] = Al + zb * sA + (long)row0 * K;
        gT[2] = Bh + zb * sB + (long)col0 * K;
        gT[3] = Bl + zb * sB + (long)col0 * K;
    } else {
        gT[1] = Bh + zb * sB + (long)col0 * K;
        gT[2] = Bl + zb * sB + (long)col0 * K;
    }

    const int niter = K >> 5;

    auto load_stage = [&](int it, int stage) {
        const int kk = it * 32;
        #pragma unroll
        for (int t = 0; t < 2 * TILES; t++) {
            int c    = t * 256 + tid;
            int tile = c >> 9;             // 512 cp.async per tile
            int row  = (c >> 2) & 127;
            int seg  = c & 3;              // 4 x 8-half segments per row
            const __half* g = gT[tile] + (long)row * K + kk + seg * 8;
            uint32_t s = sbase +
                (uint32_t)(stage * STAGE_B + tile * 10240 + row * 80 + seg * 16);
            cp_async16(s, g);
        }
    };

    float acc[4][4][4] = {};

    load_stage(0, 0);
    asm volatile("cp.async.commit_group;" ::: "memory");
    load_stage(1, 1);
    asm volatile("cp.async.commit_group;" ::: "memory");
    load_stage(2, 2);
    asm volatile("cp.async.commit_group;" ::: "memory");

    for (int it = 0; it < niter; ++it) {
        asm volatile("cp.async.wait_group 2;" ::: "memory");
        __syncthreads();

        const int buf = it % 3;
        const __half* st  = smh + buf * STAGE_H;
        const __half* sAh = st;
        const __half* sAl = (TERMS == 3) ? st + 5120 : nullptr;
        const __half* sBh = (TERMS == 3) ? st + 10240 : st + 5120;
        const __half* sBl = (TERMS == 3) ? st + 15360 : st + 10240;

        #pragma unroll
        for (int k16 = 0; k16 < 2; k16++) {
            const int kb = k16 * 16 + 2 * tnum;   // first half of k-pair

            uint32_t bh[4][2], bl[4][2];
            #pragma unroll
            for (int j = 0; j < 4; j++) {
                const int n = warp_n * 32 + j * 8 + gid;
                const __half* pb = sBh + n * 40 + kb;
                const __half* ql = sBl + n * 40 + kb;
                bh[j][0] = ld32(pb);     bh[j][1] = ld32(pb + 8);
                bl[j][0] = ld32(ql);     bl[j][1] = ld32(ql + 8);
            }
            #pragma unroll
            for (int i = 0; i < 4; i++) {
                const int r = warp_m * 64 + i * 16 + gid;
                const __half* pa = sAh + r * 40 + kb;
                uint32_t ah[4];
                ah[0] = ld32(pa);        ah[1] = ld32(pa + 320);   // r+8
                ah[2] = ld32(pa + 8);    ah[3] = ld32(pa + 328);
                uint32_t al[4];
                if (TERMS == 3) {
                    const __half* qa = sAl + r * 40 + kb;
                    al[0] = ld32(qa);        al[1] = ld32(qa + 320);
                    al[2] = ld32(qa + 8);    al[3] = ld32(qa + 328);
                }
                #pragma unroll
                for (int j = 0; j < 4; j++) {
                    mma_f16(acc[i][j], ah, bh[j]);       // hi*hi
                    mma_f16(acc[i][j], ah, bl[j]);       // hi*lo
                    if (TERMS == 3)
                        mma_f16(acc[i][j], al, bh[j]);   // lo*hi
                }
            }
        }
        __syncthreads();
        if (it + 3 < niter) load_stage(it + 3, buf);
        asm volatile("cp.async.commit_group;" ::: "memory");
    }

    // Epilogue
    #pragma unroll
    for (int i = 0; i < 4; i++) {
        const int r = row0 + warp_m * 64 + i * 16 + gid;
        #pragma unroll
        for (int j = 0; j < 4; j++) {
            const int cc = col0 + warp_n * 32 + j * 8 + 2 * tnum;
            if (SPLITOUT) {
                __half h0, l0, h1, l1;
                long o0 = (long)r * ldc + cc + zb * sC;
                long o1 = (long)(r + 8) * ldc + cc + zb * sC;
                split_h(acc[i][j][0], h0, l0);
                split_h(acc[i][j][1], h1, l1);
                *reinterpret_cast<__half2*>(Ch + o0) = __halves2half2(h0, h1);
                *reinterpret_cast<__half2*>(Cl + o0) = __halves2half2(l0, l1);
                split_h(acc[i][j][2], h0, l0);
                split_h(acc[i][j][3], h1, l1);
                *reinterpret_cast<__half2*>(Ch + o1) = __halves2half2(h0, h1);
                *reinterpret_cast<__half2*>(Cl + o1) = __halves2half2(l0, l1);
            } else {
                float* Cb = C + zb * sC;
                *reinterpret_cast<float2*>(&Cb[(long)r * ldc + cc]) =
                    make_float2(acc[i][j][0], acc[i][j][1]);
                *reinterpret_cast<float2*>(&Cb[(long)(r + 8) * ldc + cc]) =
                    make_float2(acc[i][j][2], acc[i][j][3]);
            }
        }
    }
}

// ---------------------------------------------------------------------------
// Masked row softmax (SK=2048) in place + fused single-fp16 P for the P@V
// GEMM (P rounding rel err ~2^-12; output gated at 1e-3 L2 rel err).
// Mask is int32. All-masked row -> uniform 1/SK.
// ---------------------------------------------------------------------------
__global__ __launch_bounds__(256)
void softmax_split(float* __restrict__ S, const int* __restrict__ mask,
                   __half* __restrict__ Ph)
{
    const int row = blockIdx.x;
    const int b   = row / LQ;
    float* p = S + (long)row * SK;
    __half* ph = Ph + (long)row * SK;
    const int* m = mask + (long)b * SK;
    const int t = threadIdx.x;

    __shared__ float red[256];

    float vals[8];
    int mk[8];
    float mx = -INFINITY;
    #pragma unroll
    for (int i = 0; i < 8; i++) {
        const int c = t + i * 256;
        vals[i] = p[c];
        mk[i]   = m[c];
        if (mk[i]) mx = fmaxf(mx, vals[i]);
    }
    red[t] = mx; __syncthreads();
    for (int s = 128; s > 0; s >>= 1) {
        if (t < s) red[t] = fmaxf(red[t], red[t + s]);
        __syncthreads();
    }
    mx = red[0];
    __syncthreads();

    if (!isfinite(mx)) {
        const float u = 1.0f / (float)SK;
        const __half uh = __float2half_rn(u);
        #pragma unroll
        for (int i = 0; i < 8; i++) {
            p[t + i * 256]  = u;
            ph[t + i * 256] = uh;
        }
        return;
    }

    float sum = 0.f;
    #pragma unroll
    for (int i = 0; i < 8; i++) {
        float e = mk[i] ? expf(vals[i] - mx) : 0.f;
        vals[i] = e;
        sum += e;
    }
    red[t] = sum; __syncthreads();
    for (int s = 128; s > 0; s >>= 1) {
        if (t < s) red[t] += red[t + s];
        __syncthreads();
    }
    const float inv = 1.0f / red[0];
    #pragma unroll
    for (int i = 0; i < 8; i++) {
        const int c = t + i * 256;
        float pv = vals[i] * inv;
        p[c] = pv;
        ph[c] = __float2half_rn(pv);
    }
}

// ---------------------------------------------------------------------------
// kernel_launch
// Inputs: query, key, value, W, mask. Output: [output_value | score] fp32.
// ---------------------------------------------------------------------------
extern "C" void kernel_launch(void* const* d_in, const int* in_sizes, int n_in,
                              void* d_out, int out_size)
{
    const float* q    = (const float*)d_in[0];
    const float* kk   = (const float*)d_in[1];
    const float* v    = (const float*)d_in[2];
    const float* W    = (const float*)d_in[3];
    const int*   mask = (const int*)d_in[4];

    float* oval  = (float*)d_out;                       // [4,2048,1024]
    float* score = oval + (long)BATCH * LQ * D;         // [4,2048,2048]

    __half* arena = nullptr;
    cudaGetSymbolAddress((void**)&arena, g_arena);
    __half* A1h = arena;                                // 8M
    __half* A1l = arena + (long) 8 * MH;                // 8M
    __half* Bh  = arena + (long)16 * MH;                // 8M
    __half* Bl  = arena + (long)24 * MH;                // 8M
    __half* A2h = arena + (long)32 * MH;                // 16M
    __half* A2l = arena + (long)48 * MH;                // 16M

    const int SMEM3 = 3 * 40960;                        // 3-term stages
    const int SMEM2 = 3 * 30720;                        // 2-term stages
    static bool attr_set = false;
    if (!attr_set) {
        cudaFuncSetAttribute(mma3gemm<3, true>,
            cudaFuncAttributeMaxDynamicSharedMemorySize, SMEM3);
        cudaFuncSetAttribute(mma3gemm<3, false>,
            cudaFuncAttributeMaxDynamicSharedMemorySize, SMEM3);
        cudaFuncSetAttribute(mma3gemm<2, false>,
            cudaFuncAttributeMaxDynamicSharedMemorySize, SMEM2);
        attr_set = true;
    }

    // ---- Phase 1: QW = Q @ W, result written directly as split halves ----
    split_f16<<<(BATCH * LQ * (long)D) / 1024, 256>>>(
        (const float4*)q, (__half2*)A1h, (__half2*)A1l);
    transpose_split<<<dim3(D / 32, D / 32, 1), 256>>>(W, Bh, Bl, D, D, 0, 0);
    mma3gemm<3, true><<<dim3(D / 128, (BATCH * LQ) / 128, 1), 256, SMEM3>>>(
        A1h, A1l, Bh, Bl, nullptr, A2h, A2l, D, D, 0, 0, 0);

    // ---- Phase 2: S = QW @ K^T per batch ----
    split_f16<<<(BATCH * SK * (long)D) / 1024, 256>>>(
        (const float4*)kk, (__half2*)Bh, (__half2*)Bl);
    mma3gemm<3, false><<<dim3(SK / 128, LQ / 128, BATCH), 256, SMEM3>>>(
        A2h, A2l, Bh, Bl, score, nullptr, nullptr, D, SK,
        (long)LQ * D, (long)SK * D, (long)LQ * SK);

    // ---- Phase 3: softmax (+fused fp16 P), then O = P @ V per batch ----
    softmax_split<<<BATCH * LQ, 256>>>(score, mask, A2h);
    transpose_split<<<dim3(D / 32, SK / 32, BATCH), 256>>>(
        v, Bh, Bl, SK, D, (long)SK * D, (long)D * SK);
    mma3gemm<2, false><<<dim3(D / 128, LQ / 128, BATCH), 256, SMEM2>>>(
        A2h, nullptr, Bh, Bl, oval, nullptr, nullptr, SK, D,
        (long)LQ * SK, (long)D * SK, (long)LQ * D);
}

// round 16
// speedup vs baseline: 4.8703x; 1.1398x over previous
#include <cuda_runtime.h>
#include <cuda_fp16.h>
#include <math.h>
#include <stdint.h>

// Problem shape (fixed)
static const int BATCH = 4;
static const int LQ    = 2048;
static const int SK    = 2048;
static const int D     = 1024;

// Static arena (no allocs). Layout in __half units:
//   A1h @ 0    (8M)  : Q hi            [8192,1024]
//   A1l @ 8M   (8M)  : Q lo
//   Bh  @ 16M  (8M)  : W^T / K / V^T hi
//   Bl  @ 24M  (8M)  : lo
//   A2h @ 32M  (16M) : QW hi -> P (single fp16)  [8192,1024] then [8192,2048]
//   A2l @ 48M  (16M) : QW lo
#define MH (1024*1024)
__device__ __half g_arena[(size_t)64 * MH];

// ---------------------------------------------------------------------------
// helpers
// ---------------------------------------------------------------------------
__device__ __forceinline__ uint32_t smem_u32(const void* p) {
    uint32_t a;
    asm("{ .reg .u64 t; cvta.to.shared.u64 t, %1; cvt.u32.u64 %0, t; }"
        : "=r"(a) : "l"(p));
    return a;
}

__device__ __forceinline__ void cp_async16(uint32_t s, const void* g) {
    asm volatile("cp.async.cg.shared.global [%0], [%1], 16;" :: "r"(s), "l"(g));
}

__device__ __forceinline__ uint32_t ld32(const __half* p) {
    return *reinterpret_cast<const uint32_t*>(p);
}

__device__ __forceinline__ void mma_f16(float* c, const uint32_t* a,
                                        const uint32_t* b) {
    asm volatile(
        "mma.sync.aligned.m16n8k16.row.col.f32.f16.f16.f32 "
        "{%0,%1,%2,%3}, {%4,%5,%6,%7}, {%8,%9}, {%0,%1,%2,%3};"
        : "+f"(c[0]), "+f"(c[1]), "+f"(c[2]), "+f"(c[3])
        : "r"(a[0]), "r"(a[1]), "r"(a[2]), "r"(a[3]), "r"(b[0]), "r"(b[1]));
}

__device__ __forceinline__ void split_h(float x, __half& h, __half& l) {
    h = __float2half_rn(x);
    l = __float2half_rn(x - __half2float(h));
}

// ---------------------------------------------------------------------------
// Elementwise fp16 split: h = f16(x), l = f16(x - h).  n % 1024 == 0.
// ---------------------------------------------------------------------------
__global__ __launch_bounds__(256)
void split_f16(const float4* __restrict__ in, __half2* __restrict__ h,
               __half2* __restrict__ l)
{
    const long i = (long)blockIdx.x * 256 + threadIdx.x;
    float4 x = in[i];
    __half hx, lx, hy, ly, hz, lz, hw, lw;
    split_h(x.x, hx, lx); split_h(x.y, hy, ly);
    split_h(x.z, hz, lz); split_h(x.w, hw, lw);
    h[2 * i]     = __halves2half2(hx, hy);
    h[2 * i + 1] = __halves2half2(hz, hw);
    l[2 * i]     = __halves2half2(lx, ly);
    l[2 * i + 1] = __halves2half2(lz, lw);
}

// ---------------------------------------------------------------------------
// Transpose + fp16 split: out_{h,l}[c][r] = split(in[r][c]).  32x32 tiles.
// ---------------------------------------------------------------------------
__global__ __launch_bounds__(256)
void transpose_split(const float* __restrict__ in, __half* __restrict__ oh,
                     __half* __restrict__ ol, int R, int Cn, long sIn, long sOut)
{
    __shared__ float t[32][33];
    const float* ib = in + (long)blockIdx.z * sIn;
    __half* ohb = oh + (long)blockIdx.z * sOut;
    __half* olb = ol + (long)blockIdx.z * sOut;
    const int r0 = blockIdx.y * 32, c0 = blockIdx.x * 32;
    const int tx = threadIdx.x & 31, ty = threadIdx.x >> 5;   // 32x8
    #pragma unroll
    for (int i = 0; i < 32; i += 8)
        t[ty + i][tx] = ib[(long)(r0 + ty + i) * Cn + c0 + tx];
    __syncthreads();
    #pragma unroll
    for (int i = 0; i < 32; i += 8) {
        __half h, l;
        split_h(t[tx][ty + i], h, l);
        long o = (long)(c0 + ty + i) * R + r0 + tx;
        ohb[o] = h;
        olb[o] = l;
    }
}

// ---------------------------------------------------------------------------
// fp16 multi-term GEMM (NT) via mma.sync.m16n8k16:
// TERMS=3: C = (Ah+Al)(Bh+Bl)^T   (hh + hl + lh)   tiles {Ah,Al,Bh,Bl}
// TERMS=2: C = Ah(Bh+Bl)^T        (h  + l)         tiles {Ah,Bh,Bl}
// CTA 128x128, BK=32, 8 warps (2m x 4n), warp tile 64x32.
// STAGES-deep cp.async pipeline; __launch_bounds__(256,2) forces 2 CTAs/SM
// (4 warps/SMSP) to hide HMMA RAW-accumulation latency.
// SMEM rows padded to 40 halves (80 B).
// SPLITOUT: write C as fp16 hi/lo pair instead of fp32.
// ---------------------------------------------------------------------------
template <int TERMS, int STAGES, bool SPLITOUT>
__global__ __launch_bounds__(256, 2)
void mma3gemm(const __half* __restrict__ Ah, const __half* __restrict__ Al,
              const __half* __restrict__ Bh, const __half* __restrict__ Bl,
              float* __restrict__ C, __half* __restrict__ Ch,
              __half* __restrict__ Cl, int K, int ldc,
              long sA, long sB, long sC)
{
    constexpr int TILES = (TERMS == 3) ? 4 : 3;
    constexpr int STAGE_H = TILES * 5120;           // halves per stage
    constexpr int STAGE_B = STAGE_H * 2;            // bytes per stage

    extern __shared__ __half smh[];
    const uint32_t sbase = smem_u32(smh);

    const int tid = threadIdx.x, lane = tid & 31, wid = tid >> 5;
    const int warp_m = wid & 1, warp_n = wid >> 1;
    const int gid = lane >> 2, tnum = lane & 3;
    const int row0 = blockIdx.y * 128, col0 = blockIdx.x * 128;
    const long zb = blockIdx.z;

    const __half* gT[TILES];
    gT[0] = Ah + zb * sA + (long)row0 * K;
    if (TERMS == 3) {
        gT[1] = Al + zb * sA + (long)row0 * K;
        gT[2] = Bh + zb * sB + (long)col0 * K;
        gT[3] = Bl + zb * sB + (long)col0 * K;
    } else {
        gT[1] = Bh + zb * sB + (long)col0 * K;
        gT[2] = Bl + zb * sB + (long)col0 * K;
    }

    const int niter = K >> 5;

    auto load_stage = [&](int it, int stage) {
        const int kk = it * 32;
        #pragma unroll
        for (int t = 0; t < 2 * TILES; t++) {
            int c    = t * 256 + tid;
            int tile = c >> 9;             // 512 cp.async per tile
            int row  = (c >> 2) & 127;
            int seg  = c & 3;              // 4 x 8-half segments per row
            const __half* g = gT[tile] + (long)row * K + kk + seg * 8;
            uint32_t s = sbase +
                (uint32_t)(stage * STAGE_B + tile * 10240 + row * 80 + seg * 16);
            cp_async16(s, g);
        }
    };

    float acc[4][4][4] = {};

    #pragma unroll
    for (int s = 0; s < STAGES; s++) {
        load_stage(s, s);
        asm volatile("cp.async.commit_group;" ::: "memory");
    }

    for (int it = 0; it < niter; ++it) {
        if (STAGES == 2)
            asm volatile("cp.async.wait_group 1;" ::: "memory");
        else
            asm volatile("cp.async.wait_group 2;" ::: "memory");
        __syncthreads();

        const int buf = it % STAGES;
        const __half* st  = smh + buf * STAGE_H;
        const __half* sAh = st;
        const __half* sAl = (TERMS == 3) ? st + 5120 : nullptr;
        const __half* sBh = (TERMS == 3) ? st + 10240 : st + 5120;
        const __half* sBl = (TERMS == 3) ? st + 15360 : st + 10240;

        #pragma unroll
        for (int k16 = 0; k16 < 2; k16++) {
            const int kb = k16 * 16 + 2 * tnum;   // first half of k-pair

            uint32_t bh[4][2], bl[4][2];
            #pragma unroll
            for (int j = 0; j < 4; j++) {
                const int n = warp_n * 32 + j * 8 + gid;
                const __half* pb = sBh + n * 40 + kb;
                const __half* ql = sBl + n * 40 + kb;
                bh[j][0] = ld32(pb);     bh[j][1] = ld32(pb + 8);
                bl[j][0] = ld32(ql);     bl[j][1] = ld32(ql + 8);
            }
            #pragma unroll
            for (int i = 0; i < 4; i++) {
                const int r = warp_m * 64 + i * 16 + gid;
                const __half* pa = sAh + r * 40 + kb;
                uint32_t ah[4];
                ah[0] = ld32(pa);        ah[1] = ld32(pa + 320);   // r+8
                ah[2] = ld32(pa + 8);    ah[3] = ld32(pa + 328);
                uint32_t al[4];
                if (TERMS == 3) {
                    const __half* qa = sAl + r * 40 + kb;
                    al[0] = ld32(qa);        al[1] = ld32(qa + 320);
                    al[2] = ld32(qa + 8);    al[3] = ld32(qa + 328);
                }
                #pragma unroll
                for (int j = 0; j < 4; j++) {
                    mma_f16(acc[i][j], ah, bh[j]);       // hi*hi
                    mma_f16(acc[i][j], ah, bl[j]);       // hi*lo
                    if (TERMS == 3)
                        mma_f16(acc[i][j], al, bh[j]);   // lo*hi
                }
            }
        }
        __syncthreads();
        if (it + STAGES < niter) load_stage(it + STAGES, it % STAGES);
        asm volatile("cp.async.commit_group;" ::: "memory");
    }

    // Epilogue
    #pragma unroll
    for (int i = 0; i < 4; i++) {
        const int r = row0 + warp_m * 64 + i * 16 + gid;
        #pragma unroll
        for (int j = 0; j < 4; j++) {
            const int cc = col0 + warp_n * 32 + j * 8 + 2 * tnum;
            if (SPLITOUT) {
                __half h0, l0, h1, l1;
                long o0 = (long)r * ldc + cc + zb * sC;
                long o1 = (long)(r + 8) * ldc + cc + zb * sC;
                split_h(acc[i][j][0], h0, l0);
                split_h(acc[i][j][1], h1, l1);
                *reinterpret_cast<__half2*>(Ch + o0) = __halves2half2(h0, h1);
                *reinterpret_cast<__half2*>(Cl + o0) = __halves2half2(l0, l1);
                split_h(acc[i][j][2], h0, l0);
                split_h(acc[i][j][3], h1, l1);
                *reinterpret_cast<__half2*>(Ch + o1) = __halves2half2(h0, h1);
                *reinterpret_cast<__half2*>(Cl + o1) = __halves2half2(l0, l1);
            } else {
                float* Cb = C + zb * sC;
                *reinterpret_cast<float2*>(&Cb[(long)r * ldc + cc]) =
                    make_float2(acc[i][j][0], acc[i][j][1]);
                *reinterpret_cast<float2*>(&Cb[(long)(r + 8) * ldc + cc]) =
                    make_float2(acc[i][j][2], acc[i][j][3]);
            }
        }
    }
}

// ---------------------------------------------------------------------------
// Masked row softmax (SK=2048) in place + fused single-fp16 P for the P@V
// GEMM (P rounding rel err ~2^-12; output gated at 1e-3 L2 rel err).
// Mask is int32. All-masked row -> uniform 1/SK.
// ---------------------------------------------------------------------------
__global__ __launch_bounds__(256)
void softmax_split(float* __restrict__ S, const int* __restrict__ mask,
                   __half* __restrict__ Ph)
{
    const int row = blockIdx.x;
    const int b   = row / LQ;
    float* p = S + (long)row * SK;
    __half* ph = Ph + (long)row * SK;
    const int* m = mask + (long)b * SK;
    const int t = threadIdx.x;

    __shared__ float red[256];

    float vals[8];
    int mk[8];
    float mx = -INFINITY;
    #pragma unroll
    for (int i = 0; i < 8; i++) {
        const int c = t + i * 256;
        vals[i] = p[c];
        mk[i]   = m[c];
        if (mk[i]) mx = fmaxf(mx, vals[i]);
    }
    red[t] = mx; __syncthreads();
    for (int s = 128; s > 0; s >>= 1) {
        if (t < s) red[t] = fmaxf(red[t], red[t + s]);
        __syncthreads();
    }
    mx = red[0];
    __syncthreads();

    if (!isfinite(mx)) {
        const float u = 1.0f / (float)SK;
        const __half uh = __float2half_rn(u);
        #pragma unroll
        for (int i = 0; i < 8; i++) {
            p[t + i * 256]  = u;
            ph[t + i * 256] = uh;
        }
        return;
    }

    float sum = 0.f;
    #pragma unroll
    for (int i = 0; i < 8; i++) {
        float e = mk[i] ? expf(vals[i] - mx) : 0.f;
        vals[i] = e;
        sum += e;
    }
    red[t] = sum; __syncthreads();
    for (int s = 128; s > 0; s >>= 1) {
        if (t < s) red[t] += red[t + s];
        __syncthreads();
    }
    const float inv = 1.0f / red[0];
    #pragma unroll
    for (int i = 0; i < 8; i++) {
        const int c = t + i * 256;
        float pv = vals[i] * inv;
        p[c] = pv;
        ph[c] = __float2half_rn(pv);
    }
}

// ---------------------------------------------------------------------------
// kernel_launch
// Inputs: query, key, value, W, mask. Output: [output_value | score] fp32.
// ---------------------------------------------------------------------------
extern "C" void kernel_launch(void* const* d_in, const int* in_sizes, int n_in,
                              void* d_out, int out_size)
{
    const float* q    = (const float*)d_in[0];
    const float* kk   = (const float*)d_in[1];
    const float* v    = (const float*)d_in[2];
    const float* W    = (const float*)d_in[3];
    const int*   mask = (const int*)d_in[4];

    float* oval  = (float*)d_out;                       // [4,2048,1024]
    float* score = oval + (long)BATCH * LQ * D;         // [4,2048,2048]

    __half* arena = nullptr;
    cudaGetSymbolAddress((void**)&arena, g_arena);
    __half* A1h = arena;                                // 8M
    __half* A1l = arena + (long) 8 * MH;                // 8M
    __half* Bh  = arena + (long)16 * MH;                // 8M
    __half* Bl  = arena + (long)24 * MH;                // 8M
    __half* A2h = arena + (long)32 * MH;                // 16M
    __half* A2l = arena + (long)48 * MH;                // 16M

    const int SMEM3 = 2 * 40960;                        // 3-term, 2 stages
    const int SMEM2 = 3 * 30720;                        // 2-term, 3 stages
    static bool attr_set = false;
    if (!attr_set) {
        cudaFuncSetAttribute((const void*)mma3gemm<3, 2, true>,
            cudaFuncAttributeMaxDynamicSharedMemorySize, SMEM3);
        cudaFuncSetAttribute((const void*)mma3gemm<3, 2, false>,
            cudaFuncAttributeMaxDynamicSharedMemorySize, SMEM3);
        cudaFuncSetAttribute((const void*)mma3gemm<2, 3, false>,
            cudaFuncAttributeMaxDynamicSharedMemorySize, SMEM2);
        attr_set = true;
    }

    // ---- Phase 1: QW = Q @ W, result written directly as split halves ----
    split_f16<<<(BATCH * LQ * (long)D) / 1024, 256>>>(
        (const float4*)q, (__half2*)A1h, (__half2*)A1l);
    transpose_split<<<dim3(D / 32, D / 32, 1), 256>>>(W, Bh, Bl, D, D, 0, 0);
    mma3gemm<3, 2, true><<<dim3(D / 128, (BATCH * LQ) / 128, 1), 256, SMEM3>>>(
        A1h, A1l, Bh, Bl, nullptr, A2h, A2l, D, D, 0, 0, 0);

    // ---- Phase 2: S = QW @ K^T per batch ----
    split_f16<<<(BATCH * SK * (long)D) / 1024, 256>>>(
        (const float4*)kk, (__half2*)Bh, (__half2*)Bl);
    mma3gemm<3, 2, false><<<dim3(SK / 128, LQ / 128, BATCH), 256, SMEM3>>>(
        A2h, A2l, Bh, Bl, score, nullptr, nullptr, D, SK,
        (long)LQ * D, (long)SK * D, (long)LQ * SK);

    // ---- Phase 3: softmax (+fused fp16 P), then O = P @ V per batch ----
    softmax_split<<<BATCH * LQ, 256>>>(score, mask, A2h);
    transpose_split<<<dim3(D / 32, SK / 32, BATCH), 256>>>(
        v, Bh, Bl, SK, D, (long)SK * D, (long)D * SK);
    mma3gemm<2, 3, false><<<dim3(D / 128, LQ / 128, BATCH), 256, SMEM2>>>(
        A2h, nullptr, Bh, Bl, oval, nullptr, nullptr, SK, D,
        (long)LQ * SK, (long)D * SK, (long)LQ * D);
}